// round 7
// baseline (speedup 1.0000x reference)
#include <cuda_runtime.h>
#include <math.h>
#include <stdint.h>

// ----------------------------------------------------------------------------
// Problem constants
// ----------------------------------------------------------------------------
#define B_    64
#define T_    512
#define NI_   64
#define H_    1024
#define TH_   256          // T_HARM == T_SPIKE == 256
#define DTs   0.042f

static const size_t OFF_HZS = (size_t)B_ * T_ * H_;            // 33,554,432
static const size_t OFF_US  = 2ull * (size_t)B_ * T_ * H_;     // 67,108,864
static const size_t OFF_SPK = OFF_US + (size_t)B_ * TH_ * H_;  // 83,886,080

// ----------------------------------------------------------------------------
// Device scratch (static __device__ globals: allocation-free rule)
// ----------------------------------------------------------------------------
__device__ float  g_xw[(size_t)TH_ * B_ * H_];   // [t][b][h], 64 MB
__device__ float2 g_hy2[2][32 * H_];             // ping-pong hy, pair-packed [p][h]
__device__ float2 g_hz2[2][32 * H_];             // ping-pong hz
__device__ float  g_hyWf[B_ * H_];               // hy_final @ h2h, plain [b][h]

// ----------------------------------------------------------------------------
// Helpers
// ----------------------------------------------------------------------------
__device__ __forceinline__ float2 ffma2(float2 a, float2 b, float2 c) {
    float2 d;
    asm("fma.rn.f32x2 %0, %1, %2, %3;"
        : "=l"(*reinterpret_cast<unsigned long long*>(&d))
        : "l"(*reinterpret_cast<unsigned long long*>(&a)),
          "l"(*reinterpret_cast<unsigned long long*>(&b)),
          "l"(*reinterpret_cast<unsigned long long*>(&c)));
    return d;
}

// accurate tanh, safe under fast-math (no MUFU.TANH, no overflow)
__device__ __forceinline__ float tanh_acc(float x) {
    float a = 2.0f * fabsf(x);
    float e = expf(-a);                 // in (0,1]
    float t = (1.0f - e) / (1.0f + e);
    return copysignf(t, x);
}

__device__ __forceinline__ void cp_async16(void* smem, const void* gmem) {
    unsigned s = (unsigned)__cvta_generic_to_shared(smem);
    asm volatile("cp.async.cg.shared.global [%0], [%1], 16;" :: "r"(s), "l"(gmem) : "memory");
}
#define CP_COMMIT() asm volatile("cp.async.commit_group;" ::: "memory")
#define CP_WAIT0()  asm volatile("cp.async.wait_group 0;"  ::: "memory")

// ----------------------------------------------------------------------------
// Zero the initial state buffers (must run every launch: deterministic replay)
// ----------------------------------------------------------------------------
__global__ void zero_kernel() {
    int i = blockIdx.x * 256 + threadIdx.x;
    if (i < 32 * H_) {
        g_hy2[0][i] = make_float2(0.f, 0.f);
        g_hz2[0][i] = make_float2(0.f, 0.f);
    }
}

// ----------------------------------------------------------------------------
// xw[t][b][:] = x[b][t][:] @ x2h   for t < 256  (no bias)
// grid (8 col-tiles of 128, 512 row-tiles of 32), 256 threads
// rows r = t*64 + b  (b fastest)
// ----------------------------------------------------------------------------
__global__ void __launch_bounds__(256)
xw_kernel(const float* __restrict__ x, const float* __restrict__ x2h) {
    __shared__ float xs[32][68];     // [row][k], padded
    __shared__ float ws[64][128];    // [k][col]

    const int tid = threadIdx.x;
    const int j0  = blockIdx.x * 128;
    const int r0g = blockIdx.y * 32;

    // load x tile: 512 float4, 2 per thread
    #pragma unroll
    for (int u = 0; u < 2; ++u) {
        int n = u * 256 + tid;
        int r = n >> 4, k4 = n & 15;
        int rg = r0g + r;
        int b = rg & 63, tt = rg >> 6;
        float4 v = *(const float4*)(x + ((size_t)b * T_ + tt) * NI_ + k4 * 4);
        *(float4*)&xs[r][k4 * 4] = v;
    }
    // load w tile: 2048 float4, 8 per thread
    #pragma unroll
    for (int u = 0; u < 8; ++u) {
        int n = u * 256 + tid;
        int k = n >> 5, jg = n & 31;
        float4 v = *(const float4*)(x2h + (size_t)k * H_ + j0 + jg * 4);
        *(float4*)&ws[k][jg * 4] = v;
    }
    __syncthreads();

    const int jj0 = (tid & 31) * 4;
    const int r0  = (tid >> 5) * 4;
    float acc[4][4] = {};
    #pragma unroll 8
    for (int k = 0; k < 64; ++k) {
        float4 wv = *(const float4*)&ws[k][jj0];
        #pragma unroll
        for (int r = 0; r < 4; ++r) {
            float xv = xs[r0 + r][k];
            acc[r][0] = fmaf(xv, wv.x, acc[r][0]);
            acc[r][1] = fmaf(xv, wv.y, acc[r][1]);
            acc[r][2] = fmaf(xv, wv.z, acc[r][2]);
            acc[r][3] = fmaf(xv, wv.w, acc[r][3]);
        }
    }
    #pragma unroll
    for (int r = 0; r < 4; ++r) {
        int rg = r0g + r0 + r;
        float4 v = make_float4(acc[r][0], acc[r][1], acc[r][2], acc[r][3]);
        *(float4*)&g_xw[(size_t)rg * H_ + j0 + jj0] = v;
    }
}

// ----------------------------------------------------------------------------
// Harmonic step (MODE 0) / hyW GEMM (MODE 1)
//
// grid 128 blocks x 8 output columns, 256 threads (8 warps).
// GEMM: warp w covers K-slice (128 k's, spread as 32 per 256-k tile);
//       lane = batch pair p; each thread accumulates all 8 columns
//       as 4 column-pair float2 accs per batch (FFMA2).
// hy tiles (32 pairs x 256 k, float2) double-buffered via cp.async.
// ----------------------------------------------------------------------------
#define HY_ROW   516                          // 512 + 4 pad floats
#define HY_FLOATS (2 * 32 * HY_ROW)           // 33024
#define SMEM_HARM (HY_FLOATS * 4 + 1024 * 8 * 4 + 8 * 32 * 8 * 8)  // 181,248 B

__device__ __forceinline__ void load_hy_tile(const float* __restrict__ src,
                                             float* __restrict__ hyS,
                                             int kt, int bb, int tid) {
    // 4096 float4 per tile (32 rows x 128), 16 per thread
    #pragma unroll
    for (int u = 0; u < 16; ++u) {
        int n = u * 256 + tid;
        int p = n >> 7, q = n & 127;
        cp_async16(hyS + (size_t)(bb * 32 + p) * HY_ROW + 4 * q,
                   src + ((size_t)p * H_ + (size_t)kt * 256) * 2 + 4 * q);
    }
}

template<int MODE>
__global__ void __launch_bounds__(256, 1)
harm_kernel(int t, int par,
            const float* __restrict__ h2h,
            const float* __restrict__ bias,
            const float* __restrict__ gam,
            const float* __restrict__ eps,
            float* __restrict__ out) {
    extern __shared__ float sm[];
    float*  hyS = sm;                              // [2][32][HY_ROW]
    float*  w4  = sm + HY_FLOATS;                  // [1024][8]
    float2* red = (float2*)(w4 + 1024 * 8);        // [8][32][8]

    const int tid  = threadIdx.x;
    const int lane = tid & 31;
    const int w    = tid >> 5;
    const int j0   = blockIdx.x * 8;

    const float* hyIn = (const float*)g_hy2[par];

    // weights: w4[k][c] = h2h[k][j0+c]; 8 cp.async per thread
    #pragma unroll
    for (int u = 0; u < 8; ++u) {
        int n = u * 256 + tid;
        int k = n >> 1, half = (n & 1) * 4;
        cp_async16(w4 + (size_t)k * 8 + half, h2h + (size_t)k * H_ + j0 + half);
    }
    load_hy_tile(hyIn, hyS, 0, 0, tid);
    CP_COMMIT();
    CP_WAIT0();
    __syncthreads();

    // acc[0..3] = batch 2p, col-pairs (j0+2cp, j0+2cp+1); acc[4..7] = batch 2p+1
    float2 acc[8];
    #pragma unroll
    for (int c = 0; c < 8; ++c) acc[c] = make_float2(0.f, 0.f);

    for (int kt = 0; kt < 4; ++kt) {
        if (kt < 3) { load_hy_tile(hyIn, hyS, kt + 1, (kt + 1) & 1, tid); CP_COMMIT(); }

        const float* hrow = hyS + (size_t)((kt & 1) * 32 + lane) * HY_ROW;
        const int kb  = kt * 256;
        const int kk0 = w * 32;
        #pragma unroll
        for (int kk = kk0; kk < kk0 + 32; kk += 2) {
            float4 hv = *(const float4*)(hrow + 2 * kk);
            const float* wp = w4 + (size_t)(kb + kk) * 8;
            float4 wA = *(const float4*)(wp);        // cols 0-3 @ k
            float4 wB = *(const float4*)(wp + 4);    // cols 4-7 @ k
            float4 wC = *(const float4*)(wp + 8);    // cols 0-3 @ k+1
            float4 wD = *(const float4*)(wp + 12);   // cols 4-7 @ k+1

            float2 b0k0 = make_float2(hv.x, hv.x);
            float2 b1k0 = make_float2(hv.y, hv.y);
            float2 b0k1 = make_float2(hv.z, hv.z);
            float2 b1k1 = make_float2(hv.w, hv.w);

            acc[0] = ffma2(b0k0, make_float2(wA.x, wA.y), acc[0]);
            acc[1] = ffma2(b0k0, make_float2(wA.z, wA.w), acc[1]);
            acc[2] = ffma2(b0k0, make_float2(wB.x, wB.y), acc[2]);
            acc[3] = ffma2(b0k0, make_float2(wB.z, wB.w), acc[3]);
            acc[4] = ffma2(b1k0, make_float2(wA.x, wA.y), acc[4]);
            acc[5] = ffma2(b1k0, make_float2(wA.z, wA.w), acc[5]);
            acc[6] = ffma2(b1k0, make_float2(wB.x, wB.y), acc[6]);
            acc[7] = ffma2(b1k0, make_float2(wB.z, wB.w), acc[7]);

            acc[0] = ffma2(b0k1, make_float2(wC.x, wC.y), acc[0]);
            acc[1] = ffma2(b0k1, make_float2(wC.z, wC.w), acc[1]);
            acc[2] = ffma2(b0k1, make_float2(wD.x, wD.y), acc[2]);
            acc[3] = ffma2(b0k1, make_float2(wD.z, wD.w), acc[3]);
            acc[4] = ffma2(b1k1, make_float2(wC.x, wC.y), acc[4]);
            acc[5] = ffma2(b1k1, make_float2(wC.z, wC.w), acc[5]);
            acc[6] = ffma2(b1k1, make_float2(wD.x, wD.y), acc[6]);
            acc[7] = ffma2(b1k1, make_float2(wD.z, wD.w), acc[7]);
        }
        if (kt < 3) CP_WAIT0();
        __syncthreads();
    }

    // cross-warp (K-split) reduction via smem
    #pragma unroll
    for (int c = 0; c < 8; ++c) red[(size_t)(w * 32 + lane) * 8 + c] = acc[c];
    __syncthreads();

    // finish: thread (p, c) handles batches (2p, 2p+1) at column j0+c
    const int p    = tid >> 3;
    const int c    = tid & 7;
    const int cp   = c >> 1;
    const int comp = c & 1;

    float s0 = 0.f, s1 = 0.f;
    #pragma unroll
    for (int kh = 0; kh < 8; ++kh) {
        float2 e0 = red[(size_t)(kh * 32 + p) * 8 + cp];      // batch 2p
        float2 e1 = red[(size_t)(kh * 32 + p) * 8 + 4 + cp];  // batch 2p+1
        s0 += comp ? e0.y : e0.x;
        s1 += comp ? e1.y : e1.x;
    }

    const int j  = j0 + c;
    const int b0 = 2 * p;

    if (MODE == 1) {
        g_hyWf[(size_t)b0 * H_ + j]       = s0;
        g_hyWf[(size_t)(b0 + 1) * H_ + j] = s1;
        return;
    }

    const float bj = bias[j], gj = gam[j], ej = eps[j];
    const float* xwrow = g_xw + ((size_t)t * B_ + b0) * H_ + j;
    const float x0 = xwrow[0];
    const float x1 = xwrow[H_];

    float2 hyo = g_hy2[par][(size_t)p * H_ + j];
    float2 hzo = g_hz2[par][(size_t)p * H_ + j];

    float th0 = tanh_acc(s0 + x0 + bj);
    float th1 = tanh_acc(s1 + x1 + bj);

    float hz0 = hzo.x + DTs * (th0 - gj * hyo.x - ej * hzo.x);
    float hz1 = hzo.y + DTs * (th1 - gj * hyo.y - ej * hzo.y);
    float hy0 = hyo.x + DTs * hz0;
    float hy1 = hyo.y + DTs * hz1;

    const int np = par ^ 1;
    g_hy2[np][(size_t)p * H_ + j] = make_float2(hy0, hy1);
    g_hz2[np][(size_t)p * H_ + j] = make_float2(hz0, hz1);

    out[((size_t)b0 * T_ + t) * H_ + j]                 = hy0;
    out[((size_t)(b0 + 1) * T_ + t) * H_ + j]           = hy1;
    out[OFF_HZS + ((size_t)b0 * T_ + t) * H_ + j]       = hz0;
    out[OFF_HZS + ((size_t)(b0 + 1) * T_ + t) * H_ + j] = hz1;
}

// ----------------------------------------------------------------------------
// Spiking phase: fully parallel over (b, h); 256 sequential steps per thread
// ----------------------------------------------------------------------------
__global__ void __launch_bounds__(256)
spike_kernel(float* __restrict__ out) {
    const int idx = blockIdx.x * 256 + threadIdx.x;   // 0..65535 = b*1024 + h
    const int b = idx >> 10, h = idx & 1023;

    const float hw = g_hyWf[idx];
    const float coef = (5.0f * 0.005f) * 0.042f;      // R*C*DT

    const float* xw  = g_xw + (size_t)b * H_ + h;     // + t*B_*H_
    float* us  = out + OFF_US  + (size_t)b * TH_ * H_ + h;
    float* spk = out + OFF_SPK + (size_t)b * TH_ * H_ + h;

    float u = 0.f;
    for (int t = 0; t < TH_; ++t) {
        float xv = xw[(size_t)t * (B_ * H_)];
        float s  = (u > 0.008f) ? 1.0f : 0.0f;
        if (u > 0.008f) u = 0.001f;
        u = u + (hw + xv - u) * coef;
        us[(size_t)t * H_]  = u;
        spk[(size_t)t * H_] = s;
    }
}

// ----------------------------------------------------------------------------
// Tail: hys/hzs for t in [256,512) are the final (hy, hz), copied from t=255
// ----------------------------------------------------------------------------
__global__ void __launch_bounds__(256)
tail_kernel(float* __restrict__ out) {
    const int b  = blockIdx.x;
    const int tc = blockIdx.y;        // 8 chunks of 32 timesteps
    const int h4 = threadIdx.x;       // float4 index 0..255

    const float4 hyv = ((const float4*)(out + ((size_t)b * T_ + 255) * H_))[h4];
    const float4 hzv = ((const float4*)(out + OFF_HZS + ((size_t)b * T_ + 255) * H_))[h4];

    const int t0 = 256 + tc * 32;
    for (int tt = 0; tt < 32; ++tt) {
        size_t off = ((size_t)b * T_ + t0 + tt) * H_;
        ((float4*)(out + off))[h4]           = hyv;
        ((float4*)(out + OFF_HZS + off))[h4] = hzv;
    }
}

// ----------------------------------------------------------------------------
// Launch
// ----------------------------------------------------------------------------
extern "C" void kernel_launch(void* const* d_in, const int* in_sizes, int n_in,
                              void* d_out, int out_size) {
    (void)in_sizes; (void)n_in; (void)out_size;
    const float* x    = (const float*)d_in[0];
    const float* x2h  = (const float*)d_in[1];
    const float* h2h  = (const float*)d_in[2];
    const float* bias = (const float*)d_in[3];
    const float* gam  = (const float*)d_in[4];
    const float* eps  = (const float*)d_in[5];
    float* out = (float*)d_out;

    cudaFuncSetAttribute(harm_kernel<0>, cudaFuncAttributeMaxDynamicSharedMemorySize, SMEM_HARM);
    cudaFuncSetAttribute(harm_kernel<1>, cudaFuncAttributeMaxDynamicSharedMemorySize, SMEM_HARM);

    zero_kernel<<<128, 256>>>();
    xw_kernel<<<dim3(8, 512), 256>>>(x, x2h);

    for (int t = 0; t < TH_; ++t)
        harm_kernel<0><<<128, 256, SMEM_HARM>>>(t, t & 1, h2h, bias, gam, eps, out);

    // after 256 steps the final state sits in buffer 0
    harm_kernel<1><<<128, 256, SMEM_HARM>>>(0, 0, h2h, bias, gam, eps, out);

    spike_kernel<<<256, 256>>>(out);
    tail_kernel<<<dim3(64, 8), 256>>>(out);
}

// round 8
// speedup vs baseline: 1.0012x; 1.0012x over previous
#include <cuda_runtime.h>
#include <math.h>
#include <stdint.h>

// ----------------------------------------------------------------------------
// Problem constants
// ----------------------------------------------------------------------------
#define B_    64
#define T_    512
#define NI_   64
#define H_    1024
#define TH_   256          // T_HARM == T_SPIKE == 256
#define DTs   0.042f

static const size_t OFF_HZS = (size_t)B_ * T_ * H_;            // 33,554,432
static const size_t OFF_US  = 2ull * (size_t)B_ * T_ * H_;     // 67,108,864
static const size_t OFF_SPK = OFF_US + (size_t)B_ * TH_ * H_;  // 83,886,080

// ----------------------------------------------------------------------------
// Device scratch (static __device__ globals: allocation-free rule)
// ----------------------------------------------------------------------------
__device__ float  g_xw[(size_t)TH_ * B_ * H_];   // [t][b][h], 64 MB
__device__ float2 g_hy2[2][32 * H_];             // ping-pong hy, pair-packed [p][h]
__device__ float2 g_hz2[2][32 * H_];             // ping-pong hz
__device__ float  g_hyWf[B_ * H_];               // hy_final @ h2h, plain [b][h]

// ----------------------------------------------------------------------------
// Helpers
// ----------------------------------------------------------------------------
__device__ __forceinline__ float2 ffma2(float2 a, float2 b, float2 c) {
    float2 d;
    asm("fma.rn.f32x2 %0, %1, %2, %3;"
        : "=l"(*reinterpret_cast<unsigned long long*>(&d))
        : "l"(*reinterpret_cast<unsigned long long*>(&a)),
          "l"(*reinterpret_cast<unsigned long long*>(&b)),
          "l"(*reinterpret_cast<unsigned long long*>(&c)));
    return d;
}

// accurate tanh, safe under fast-math (no MUFU.TANH, no overflow)
__device__ __forceinline__ float tanh_acc(float x) {
    float a = 2.0f * fabsf(x);
    float e = expf(-a);                 // in (0,1]
    float t = (1.0f - e) / (1.0f + e);
    return copysignf(t, x);
}

__device__ __forceinline__ void cp_async16(void* smem, const void* gmem) {
    unsigned s = (unsigned)__cvta_generic_to_shared(smem);
    asm volatile("cp.async.cg.shared.global [%0], [%1], 16;" :: "r"(s), "l"(gmem) : "memory");
}
#define CP_COMMIT() asm volatile("cp.async.commit_group;" ::: "memory")
#define CP_WAIT0()  asm volatile("cp.async.wait_group 0;"  ::: "memory")

// ----------------------------------------------------------------------------
// Zero the initial state buffers (must run every launch: deterministic replay)
// ----------------------------------------------------------------------------
__global__ void zero_kernel() {
    int i = blockIdx.x * 256 + threadIdx.x;
    if (i < 32 * H_) {
        g_hy2[0][i] = make_float2(0.f, 0.f);
        g_hz2[0][i] = make_float2(0.f, 0.f);
    }
}

// ----------------------------------------------------------------------------
// xw[t][b][:] = x[b][t][:] @ x2h   for t < 256  (no bias)
// grid (8 col-tiles of 128, 512 row-tiles of 32), 256 threads
// rows r = t*64 + b  (b fastest)
// ----------------------------------------------------------------------------
__global__ void __launch_bounds__(256)
xw_kernel(const float* __restrict__ x, const float* __restrict__ x2h) {
    __shared__ float xs[32][68];     // [row][k], padded
    __shared__ float ws[64][128];    // [k][col]

    const int tid = threadIdx.x;
    const int j0  = blockIdx.x * 128;
    const int r0g = blockIdx.y * 32;

    // load x tile: 512 float4, 2 per thread
    #pragma unroll
    for (int u = 0; u < 2; ++u) {
        int n = u * 256 + tid;
        int r = n >> 4, k4 = n & 15;
        int rg = r0g + r;
        int b = rg & 63, tt = rg >> 6;
        float4 v = *(const float4*)(x + ((size_t)b * T_ + tt) * NI_ + k4 * 4);
        *(float4*)&xs[r][k4 * 4] = v;
    }
    // load w tile: 2048 float4, 8 per thread
    #pragma unroll
    for (int u = 0; u < 8; ++u) {
        int n = u * 256 + tid;
        int k = n >> 5, jg = n & 31;
        float4 v = *(const float4*)(x2h + (size_t)k * H_ + j0 + jg * 4);
        *(float4*)&ws[k][jg * 4] = v;
    }
    __syncthreads();

    const int jj0 = (tid & 31) * 4;
    const int r0  = (tid >> 5) * 4;
    float acc[4][4] = {};
    #pragma unroll 8
    for (int k = 0; k < 64; ++k) {
        float4 wv = *(const float4*)&ws[k][jj0];
        #pragma unroll
        for (int r = 0; r < 4; ++r) {
            float xv = xs[r0 + r][k];
            acc[r][0] = fmaf(xv, wv.x, acc[r][0]);
            acc[r][1] = fmaf(xv, wv.y, acc[r][1]);
            acc[r][2] = fmaf(xv, wv.z, acc[r][2]);
            acc[r][3] = fmaf(xv, wv.w, acc[r][3]);
        }
    }
    #pragma unroll
    for (int r = 0; r < 4; ++r) {
        int rg = r0g + r0 + r;
        float4 v = make_float4(acc[r][0], acc[r][1], acc[r][2], acc[r][3]);
        *(float4*)&g_xw[(size_t)rg * H_ + j0 + jj0] = v;
    }
}

// ----------------------------------------------------------------------------
// Harmonic step (MODE 0) / hyW GEMM (MODE 1)
//
// grid 128 blocks x 8 output columns, 256 threads (8 warps).
// GEMM: warp w covers K-slice (128 k's, spread as 32 per 256-k tile);
//       lane = batch pair p; each thread accumulates all 8 columns
//       as 4 column-pair float2 accs per batch (FFMA2).
// hy tiles (32 pairs x 256 k, float2) double-buffered via cp.async.
// ----------------------------------------------------------------------------
#define HY_ROW   516                          // 512 + 4 pad floats
#define HY_FLOATS (2 * 32 * HY_ROW)           // 33024
#define SMEM_HARM (HY_FLOATS * 4 + 1024 * 8 * 4 + 8 * 32 * 8 * 8)  // 181,248 B

__device__ __forceinline__ void load_hy_tile(const float* __restrict__ src,
                                             float* __restrict__ hyS,
                                             int kt, int bb, int tid) {
    // 4096 float4 per tile (32 rows x 128), 16 per thread
    #pragma unroll
    for (int u = 0; u < 16; ++u) {
        int n = u * 256 + tid;
        int p = n >> 7, q = n & 127;
        cp_async16(hyS + (size_t)(bb * 32 + p) * HY_ROW + 4 * q,
                   src + ((size_t)p * H_ + (size_t)kt * 256) * 2 + 4 * q);
    }
}

template<int MODE>
__global__ void __launch_bounds__(256, 1)
harm_kernel(int t, int par,
            const float* __restrict__ h2h,
            const float* __restrict__ bias,
            const float* __restrict__ gam,
            const float* __restrict__ eps,
            float* __restrict__ out) {
    extern __shared__ float sm[];
    float*  hyS = sm;                              // [2][32][HY_ROW]
    float*  w4  = sm + HY_FLOATS;                  // [1024][8]
    float2* red = (float2*)(w4 + 1024 * 8);        // [8][32][8]

    const int tid  = threadIdx.x;
    const int lane = tid & 31;
    const int w    = tid >> 5;
    const int j0   = blockIdx.x * 8;

    const float* hyIn = (const float*)g_hy2[par];

    // weights: w4[k][c] = h2h[k][j0+c]; 8 cp.async per thread
    #pragma unroll
    for (int u = 0; u < 8; ++u) {
        int n = u * 256 + tid;
        int k = n >> 1, half = (n & 1) * 4;
        cp_async16(w4 + (size_t)k * 8 + half, h2h + (size_t)k * H_ + j0 + half);
    }
    load_hy_tile(hyIn, hyS, 0, 0, tid);
    CP_COMMIT();
    CP_WAIT0();
    __syncthreads();

    // acc[0..3] = batch 2p, col-pairs (j0+2cp, j0+2cp+1); acc[4..7] = batch 2p+1
    float2 acc[8];
    #pragma unroll
    for (int c = 0; c < 8; ++c) acc[c] = make_float2(0.f, 0.f);

    for (int kt = 0; kt < 4; ++kt) {
        if (kt < 3) { load_hy_tile(hyIn, hyS, kt + 1, (kt + 1) & 1, tid); CP_COMMIT(); }

        const float* hrow = hyS + (size_t)((kt & 1) * 32 + lane) * HY_ROW;
        const int kb  = kt * 256;
        const int kk0 = w * 32;
        #pragma unroll
        for (int kk = kk0; kk < kk0 + 32; kk += 2) {
            float4 hv = *(const float4*)(hrow + 2 * kk);
            const float* wp = w4 + (size_t)(kb + kk) * 8;
            float4 wA = *(const float4*)(wp);        // cols 0-3 @ k
            float4 wB = *(const float4*)(wp + 4);    // cols 4-7 @ k
            float4 wC = *(const float4*)(wp + 8);    // cols 0-3 @ k+1
            float4 wD = *(const float4*)(wp + 12);   // cols 4-7 @ k+1

            float2 b0k0 = make_float2(hv.x, hv.x);
            float2 b1k0 = make_float2(hv.y, hv.y);
            float2 b0k1 = make_float2(hv.z, hv.z);
            float2 b1k1 = make_float2(hv.w, hv.w);

            acc[0] = ffma2(b0k0, make_float2(wA.x, wA.y), acc[0]);
            acc[1] = ffma2(b0k0, make_float2(wA.z, wA.w), acc[1]);
            acc[2] = ffma2(b0k0, make_float2(wB.x, wB.y), acc[2]);
            acc[3] = ffma2(b0k0, make_float2(wB.z, wB.w), acc[3]);
            acc[4] = ffma2(b1k0, make_float2(wA.x, wA.y), acc[4]);
            acc[5] = ffma2(b1k0, make_float2(wA.z, wA.w), acc[5]);
            acc[6] = ffma2(b1k0, make_float2(wB.x, wB.y), acc[6]);
            acc[7] = ffma2(b1k0, make_float2(wB.z, wB.w), acc[7]);

            acc[0] = ffma2(b0k1, make_float2(wC.x, wC.y), acc[0]);
            acc[1] = ffma2(b0k1, make_float2(wC.z, wC.w), acc[1]);
            acc[2] = ffma2(b0k1, make_float2(wD.x, wD.y), acc[2]);
            acc[3] = ffma2(b0k1, make_float2(wD.z, wD.w), acc[3]);
            acc[4] = ffma2(b1k1, make_float2(wC.x, wC.y), acc[4]);
            acc[5] = ffma2(b1k1, make_float2(wC.z, wC.w), acc[5]);
            acc[6] = ffma2(b1k1, make_float2(wD.x, wD.y), acc[6]);
            acc[7] = ffma2(b1k1, make_float2(wD.z, wD.w), acc[7]);
        }
        if (kt < 3) CP_WAIT0();
        __syncthreads();
    }

    // cross-warp (K-split) reduction via smem
    #pragma unroll
    for (int c = 0; c < 8; ++c) red[(size_t)(w * 32 + lane) * 8 + c] = acc[c];
    __syncthreads();

    // finish: thread (p, c) handles batches (2p, 2p+1) at column j0+c
    const int p    = tid >> 3;
    const int c    = tid & 7;
    const int cp   = c >> 1;
    const int comp = c & 1;

    float s0 = 0.f, s1 = 0.f;
    #pragma unroll
    for (int kh = 0; kh < 8; ++kh) {
        float2 e0 = red[(size_t)(kh * 32 + p) * 8 + cp];      // batch 2p
        float2 e1 = red[(size_t)(kh * 32 + p) * 8 + 4 + cp];  // batch 2p+1
        s0 += comp ? e0.y : e0.x;
        s1 += comp ? e1.y : e1.x;
    }

    const int j  = j0 + c;
    const int b0 = 2 * p;

    if (MODE == 1) {
        g_hyWf[(size_t)b0 * H_ + j]       = s0;
        g_hyWf[(size_t)(b0 + 1) * H_ + j] = s1;
        return;
    }

    const float bj = bias[j], gj = gam[j], ej = eps[j];
    const float* xwrow = g_xw + ((size_t)t * B_ + b0) * H_ + j;
    const float x0 = xwrow[0];
    const float x1 = xwrow[H_];

    float2 hyo = g_hy2[par][(size_t)p * H_ + j];
    float2 hzo = g_hz2[par][(size_t)p * H_ + j];

    float th0 = tanh_acc(s0 + x0 + bj);
    float th1 = tanh_acc(s1 + x1 + bj);

    float hz0 = hzo.x + DTs * (th0 - gj * hyo.x - ej * hzo.x);
    float hz1 = hzo.y + DTs * (th1 - gj * hyo.y - ej * hzo.y);
    float hy0 = hyo.x + DTs * hz0;
    float hy1 = hyo.y + DTs * hz1;

    const int np = par ^ 1;
    g_hy2[np][(size_t)p * H_ + j] = make_float2(hy0, hy1);
    g_hz2[np][(size_t)p * H_ + j] = make_float2(hz0, hz1);

    out[((size_t)b0 * T_ + t) * H_ + j]                 = hy0;
    out[((size_t)(b0 + 1) * T_ + t) * H_ + j]           = hy1;
    out[OFF_HZS + ((size_t)b0 * T_ + t) * H_ + j]       = hz0;
    out[OFF_HZS + ((size_t)(b0 + 1) * T_ + t) * H_ + j] = hz1;
}

// ----------------------------------------------------------------------------
// Spiking phase: fully parallel over (b, h); 256 sequential steps per thread
// ----------------------------------------------------------------------------
__global__ void __launch_bounds__(256)
spike_kernel(float* __restrict__ out) {
    const int idx = blockIdx.x * 256 + threadIdx.x;   // 0..65535 = b*1024 + h
    const int b = idx >> 10, h = idx & 1023;

    const float hw = g_hyWf[idx];
    const float coef = (5.0f * 0.005f) * 0.042f;      // R*C*DT

    const float* xw  = g_xw + (size_t)b * H_ + h;     // + t*B_*H_
    float* us  = out + OFF_US  + (size_t)b * TH_ * H_ + h;
    float* spk = out + OFF_SPK + (size_t)b * TH_ * H_ + h;

    float u = 0.f;
    for (int t = 0; t < TH_; ++t) {
        float xv = xw[(size_t)t * (B_ * H_)];
        float s  = (u > 0.008f) ? 1.0f : 0.0f;
        if (u > 0.008f) u = 0.001f;
        u = u + (hw + xv - u) * coef;
        us[(size_t)t * H_]  = u;
        spk[(size_t)t * H_] = s;
    }
}

// ----------------------------------------------------------------------------
// Tail: hys/hzs for t in [256,512) are the final (hy, hz), copied from t=255
// ----------------------------------------------------------------------------
__global__ void __launch_bounds__(256)
tail_kernel(float* __restrict__ out) {
    const int b  = blockIdx.x;
    const int tc = blockIdx.y;        // 8 chunks of 32 timesteps
    const int h4 = threadIdx.x;       // float4 index 0..255

    const float4 hyv = ((const float4*)(out + ((size_t)b * T_ + 255) * H_))[h4];
    const float4 hzv = ((const float4*)(out + OFF_HZS + ((size_t)b * T_ + 255) * H_))[h4];

    const int t0 = 256 + tc * 32;
    for (int tt = 0; tt < 32; ++tt) {
        size_t off = ((size_t)b * T_ + t0 + tt) * H_;
        ((float4*)(out + off))[h4]           = hyv;
        ((float4*)(out + OFF_HZS + off))[h4] = hzv;
    }
}

// ----------------------------------------------------------------------------
// Launch
// ----------------------------------------------------------------------------
extern "C" void kernel_launch(void* const* d_in, const int* in_sizes, int n_in,
                              void* d_out, int out_size) {
    (void)in_sizes; (void)n_in; (void)out_size;
    const float* x    = (const float*)d_in[0];
    const float* x2h  = (const float*)d_in[1];
    const float* h2h  = (const float*)d_in[2];
    const float* bias = (const float*)d_in[3];
    const float* gam  = (const float*)d_in[4];
    const float* eps  = (const float*)d_in[5];
    float* out = (float*)d_out;

    cudaFuncSetAttribute(harm_kernel<0>, cudaFuncAttributeMaxDynamicSharedMemorySize, SMEM_HARM);
    cudaFuncSetAttribute(harm_kernel<1>, cudaFuncAttributeMaxDynamicSharedMemorySize, SMEM_HARM);

    zero_kernel<<<128, 256>>>();
    xw_kernel<<<dim3(8, 512), 256>>>(x, x2h);

    for (int t = 0; t < TH_; ++t)
        harm_kernel<0><<<128, 256, SMEM_HARM>>>(t, t & 1, h2h, bias, gam, eps, out);

    // after 256 steps the final state sits in buffer 0
    harm_kernel<1><<<128, 256, SMEM_HARM>>>(0, 0, h2h, bias, gam, eps, out);

    spike_kernel<<<256, 256>>>(out);
    tail_kernel<<<dim3(64, 8), 256>>>(out);
}

// round 9
// speedup vs baseline: 1.0031x; 1.0019x over previous
#include <cuda_runtime.h>
#include <math.h>
#include <stdint.h>

// ----------------------------------------------------------------------------
// Problem constants
// ----------------------------------------------------------------------------
#define B_    64
#define T_    512
#define NI_   64
#define H_    1024
#define TH_   256          // T_HARM == T_SPIKE == 256
#define DTs   0.042f

static const size_t OFF_HZS = (size_t)B_ * T_ * H_;            // 33,554,432
static const size_t OFF_US  = 2ull * (size_t)B_ * T_ * H_;     // 67,108,864
static const size_t OFF_SPK = OFF_US + (size_t)B_ * TH_ * H_;  // 83,886,080

// ----------------------------------------------------------------------------
// Device scratch (static __device__ globals: allocation-free rule)
// ----------------------------------------------------------------------------
__device__ float  g_xw[(size_t)TH_ * B_ * H_];   // [t][b][h], 64 MB
__device__ float2 g_hy2[2][32 * H_];             // ping-pong hy, pair-packed [p][h]
__device__ float2 g_hz2[2][32 * H_];             // ping-pong hz
__device__ float  g_hyWf[B_ * H_];               // hy_final @ h2h, plain [b][h]

// ----------------------------------------------------------------------------
// Helpers
// ----------------------------------------------------------------------------
__device__ __forceinline__ float2 ffma2(float2 a, float2 b, float2 c) {
    float2 d;
    asm("fma.rn.f32x2 %0, %1, %2, %3;"
        : "=l"(*reinterpret_cast<unsigned long long*>(&d))
        : "l"(*reinterpret_cast<unsigned long long*>(&a)),
          "l"(*reinterpret_cast<unsigned long long*>(&b)),
          "l"(*reinterpret_cast<unsigned long long*>(&c)));
    return d;
}

// accurate tanh, safe under fast-math (no MUFU.TANH, no overflow)
__device__ __forceinline__ float tanh_acc(float x) {
    float a = 2.0f * fabsf(x);
    float e = expf(-a);                 // in (0,1]
    float t = (1.0f - e) / (1.0f + e);
    return copysignf(t, x);
}

__device__ __forceinline__ void cp_async16(void* smem, const void* gmem) {
    unsigned s = (unsigned)__cvta_generic_to_shared(smem);
    asm volatile("cp.async.cg.shared.global [%0], [%1], 16;" :: "r"(s), "l"(gmem) : "memory");
}
#define CP_COMMIT() asm volatile("cp.async.commit_group;" ::: "memory")
#define CP_WAIT0()  asm volatile("cp.async.wait_group 0;"  ::: "memory")

// ----------------------------------------------------------------------------
// Zero the initial state buffers (must run every launch: deterministic replay)
// ----------------------------------------------------------------------------
__global__ void zero_kernel() {
    int i = blockIdx.x * 256 + threadIdx.x;
    if (i < 32 * H_) {
        g_hy2[0][i] = make_float2(0.f, 0.f);
        g_hz2[0][i] = make_float2(0.f, 0.f);
    }
}

// ----------------------------------------------------------------------------
// xw[t][b][:] = x[b][t][:] @ x2h   for t < 256  (no bias)
// grid (8 col-tiles of 128, 512 row-tiles of 32), 256 threads
// rows r = t*64 + b  (b fastest)
// ----------------------------------------------------------------------------
__global__ void __launch_bounds__(256)
xw_kernel(const float* __restrict__ x, const float* __restrict__ x2h) {
    __shared__ float xs[32][68];     // [row][k], padded
    __shared__ float ws[64][128];    // [k][col]

    const int tid = threadIdx.x;
    const int j0  = blockIdx.x * 128;
    const int r0g = blockIdx.y * 32;

    // load x tile: 512 float4, 2 per thread
    #pragma unroll
    for (int u = 0; u < 2; ++u) {
        int n = u * 256 + tid;
        int r = n >> 4, k4 = n & 15;
        int rg = r0g + r;
        int b = rg & 63, tt = rg >> 6;
        float4 v = *(const float4*)(x + ((size_t)b * T_ + tt) * NI_ + k4 * 4);
        *(float4*)&xs[r][k4 * 4] = v;
    }
    // load w tile: 2048 float4, 8 per thread
    #pragma unroll
    for (int u = 0; u < 8; ++u) {
        int n = u * 256 + tid;
        int k = n >> 5, jg = n & 31;
        float4 v = *(const float4*)(x2h + (size_t)k * H_ + j0 + jg * 4);
        *(float4*)&ws[k][jg * 4] = v;
    }
    __syncthreads();

    const int jj0 = (tid & 31) * 4;
    const int r0  = (tid >> 5) * 4;
    float acc[4][4] = {};
    #pragma unroll 8
    for (int k = 0; k < 64; ++k) {
        float4 wv = *(const float4*)&ws[k][jj0];
        #pragma unroll
        for (int r = 0; r < 4; ++r) {
            float xv = xs[r0 + r][k];
            acc[r][0] = fmaf(xv, wv.x, acc[r][0]);
            acc[r][1] = fmaf(xv, wv.y, acc[r][1]);
            acc[r][2] = fmaf(xv, wv.z, acc[r][2]);
            acc[r][3] = fmaf(xv, wv.w, acc[r][3]);
        }
    }
    #pragma unroll
    for (int r = 0; r < 4; ++r) {
        int rg = r0g + r0 + r;
        float4 v = make_float4(acc[r][0], acc[r][1], acc[r][2], acc[r][3]);
        *(float4*)&g_xw[(size_t)rg * H_ + j0 + jj0] = v;
    }
}

// ----------------------------------------------------------------------------
// Harmonic step (MODE 0) / hyW GEMM (MODE 1)
//
// grid 128 blocks x 8 output columns, 256 threads (8 warps).
// GEMM: warp w covers K-slice (128 k's, spread as 32 per 256-k tile);
//       lane = batch pair p; each thread accumulates all 8 columns
//       as 4 column-pair float2 accs per batch (FFMA2).
// hy tiles (32 pairs x 256 k, float2) double-buffered via cp.async.
// ----------------------------------------------------------------------------
#define HY_ROW   516                          // 512 + 4 pad floats
#define HY_FLOATS (2 * 32 * HY_ROW)           // 33024
#define SMEM_HARM (HY_FLOATS * 4 + 1024 * 8 * 4 + 8 * 32 * 8 * 8)  // 181,248 B

__device__ __forceinline__ void load_hy_tile(const float* __restrict__ src,
                                             float* __restrict__ hyS,
                                             int kt, int bb, int tid) {
    // 4096 float4 per tile (32 rows x 128), 16 per thread
    #pragma unroll
    for (int u = 0; u < 16; ++u) {
        int n = u * 256 + tid;
        int p = n >> 7, q = n & 127;
        cp_async16(hyS + (size_t)(bb * 32 + p) * HY_ROW + 4 * q,
                   src + ((size_t)p * H_ + (size_t)kt * 256) * 2 + 4 * q);
    }
}

template<int MODE>
__global__ void __launch_bounds__(256, 1)
harm_kernel(int t, int par,
            const float* __restrict__ h2h,
            const float* __restrict__ bias,
            const float* __restrict__ gam,
            const float* __restrict__ eps,
            float* __restrict__ out) {
    extern __shared__ float sm[];
    float*  hyS = sm;                              // [2][32][HY_ROW]
    float*  w4  = sm + HY_FLOATS;                  // [1024][8]
    float2* red = (float2*)(w4 + 1024 * 8);        // [8][32][8]

    const int tid  = threadIdx.x;
    const int lane = tid & 31;
    const int w    = tid >> 5;
    const int j0   = blockIdx.x * 8;

    const float* hyIn = (const float*)g_hy2[par];

    // weights: w4[k][c] = h2h[k][j0+c]; 8 cp.async per thread
    #pragma unroll
    for (int u = 0; u < 8; ++u) {
        int n = u * 256 + tid;
        int k = n >> 1, half = (n & 1) * 4;
        cp_async16(w4 + (size_t)k * 8 + half, h2h + (size_t)k * H_ + j0 + half);
    }
    load_hy_tile(hyIn, hyS, 0, 0, tid);
    CP_COMMIT();
    CP_WAIT0();
    __syncthreads();

    // acc[0..3] = batch 2p, col-pairs (j0+2cp, j0+2cp+1); acc[4..7] = batch 2p+1
    float2 acc[8];
    #pragma unroll
    for (int c = 0; c < 8; ++c) acc[c] = make_float2(0.f, 0.f);

    for (int kt = 0; kt < 4; ++kt) {
        if (kt < 3) { load_hy_tile(hyIn, hyS, kt + 1, (kt + 1) & 1, tid); CP_COMMIT(); }

        const float* hrow = hyS + (size_t)((kt & 1) * 32 + lane) * HY_ROW;
        const int kb  = kt * 256;
        const int kk0 = w * 32;
        #pragma unroll
        for (int kk = kk0; kk < kk0 + 32; kk += 2) {
            float4 hv = *(const float4*)(hrow + 2 * kk);
            const float* wp = w4 + (size_t)(kb + kk) * 8;
            float4 wA = *(const float4*)(wp);        // cols 0-3 @ k
            float4 wB = *(const float4*)(wp + 4);    // cols 4-7 @ k
            float4 wC = *(const float4*)(wp + 8);    // cols 0-3 @ k+1
            float4 wD = *(const float4*)(wp + 12);   // cols 4-7 @ k+1

            float2 b0k0 = make_float2(hv.x, hv.x);
            float2 b1k0 = make_float2(hv.y, hv.y);
            float2 b0k1 = make_float2(hv.z, hv.z);
            float2 b1k1 = make_float2(hv.w, hv.w);

            acc[0] = ffma2(b0k0, make_float2(wA.x, wA.y), acc[0]);
            acc[1] = ffma2(b0k0, make_float2(wA.z, wA.w), acc[1]);
            acc[2] = ffma2(b0k0, make_float2(wB.x, wB.y), acc[2]);
            acc[3] = ffma2(b0k0, make_float2(wB.z, wB.w), acc[3]);
            acc[4] = ffma2(b1k0, make_float2(wA.x, wA.y), acc[4]);
            acc[5] = ffma2(b1k0, make_float2(wA.z, wA.w), acc[5]);
            acc[6] = ffma2(b1k0, make_float2(wB.x, wB.y), acc[6]);
            acc[7] = ffma2(b1k0, make_float2(wB.z, wB.w), acc[7]);

            acc[0] = ffma2(b0k1, make_float2(wC.x, wC.y), acc[0]);
            acc[1] = ffma2(b0k1, make_float2(wC.z, wC.w), acc[1]);
            acc[2] = ffma2(b0k1, make_float2(wD.x, wD.y), acc[2]);
            acc[3] = ffma2(b0k1, make_float2(wD.z, wD.w), acc[3]);
            acc[4] = ffma2(b1k1, make_float2(wC.x, wC.y), acc[4]);
            acc[5] = ffma2(b1k1, make_float2(wC.z, wC.w), acc[5]);
            acc[6] = ffma2(b1k1, make_float2(wD.x, wD.y), acc[6]);
            acc[7] = ffma2(b1k1, make_float2(wD.z, wD.w), acc[7]);
        }
        if (kt < 3) CP_WAIT0();
        __syncthreads();
    }

    // cross-warp (K-split) reduction via smem
    #pragma unroll
    for (int c = 0; c < 8; ++c) red[(size_t)(w * 32 + lane) * 8 + c] = acc[c];
    __syncthreads();

    // finish: thread (p, c) handles batches (2p, 2p+1) at column j0+c
    const int p    = tid >> 3;
    const int c    = tid & 7;
    const int cp   = c >> 1;
    const int comp = c & 1;

    float s0 = 0.f, s1 = 0.f;
    #pragma unroll
    for (int kh = 0; kh < 8; ++kh) {
        float2 e0 = red[(size_t)(kh * 32 + p) * 8 + cp];      // batch 2p
        float2 e1 = red[(size_t)(kh * 32 + p) * 8 + 4 + cp];  // batch 2p+1
        s0 += comp ? e0.y : e0.x;
        s1 += comp ? e1.y : e1.x;
    }

    const int j  = j0 + c;
    const int b0 = 2 * p;

    if (MODE == 1) {
        g_hyWf[(size_t)b0 * H_ + j]       = s0;
        g_hyWf[(size_t)(b0 + 1) * H_ + j] = s1;
        return;
    }

    const float bj = bias[j], gj = gam[j], ej = eps[j];
    const float* xwrow = g_xw + ((size_t)t * B_ + b0) * H_ + j;
    const float x0 = xwrow[0];
    const float x1 = xwrow[H_];

    float2 hyo = g_hy2[par][(size_t)p * H_ + j];
    float2 hzo = g_hz2[par][(size_t)p * H_ + j];

    float th0 = tanh_acc(s0 + x0 + bj);
    float th1 = tanh_acc(s1 + x1 + bj);

    float hz0 = hzo.x + DTs * (th0 - gj * hyo.x - ej * hzo.x);
    float hz1 = hzo.y + DTs * (th1 - gj * hyo.y - ej * hzo.y);
    float hy0 = hyo.x + DTs * hz0;
    float hy1 = hyo.y + DTs * hz1;

    const int np = par ^ 1;
    g_hy2[np][(size_t)p * H_ + j] = make_float2(hy0, hy1);
    g_hz2[np][(size_t)p * H_ + j] = make_float2(hz0, hz1);

    out[((size_t)b0 * T_ + t) * H_ + j]                 = hy0;
    out[((size_t)(b0 + 1) * T_ + t) * H_ + j]           = hy1;
    out[OFF_HZS + ((size_t)b0 * T_ + t) * H_ + j]       = hz0;
    out[OFF_HZS + ((size_t)(b0 + 1) * T_ + t) * H_ + j] = hz1;
}

// ----------------------------------------------------------------------------
// Spiking phase: fully parallel over (b, h); 256 sequential steps per thread
// ----------------------------------------------------------------------------
__global__ void __launch_bounds__(256)
spike_kernel(float* __restrict__ out) {
    const int idx = blockIdx.x * 256 + threadIdx.x;   // 0..65535 = b*1024 + h
    const int b = idx >> 10, h = idx & 1023;

    const float hw = g_hyWf[idx];
    const float coef = (5.0f * 0.005f) * 0.042f;      // R*C*DT

    const float* xw  = g_xw + (size_t)b * H_ + h;     // + t*B_*H_
    float* us  = out + OFF_US  + (size_t)b * TH_ * H_ + h;
    float* spk = out + OFF_SPK + (size_t)b * TH_ * H_ + h;

    float u = 0.f;
    for (int t = 0; t < TH_; ++t) {
        float xv = xw[(size_t)t * (B_ * H_)];
        float s  = (u > 0.008f) ? 1.0f : 0.0f;
        if (u > 0.008f) u = 0.001f;
        u = u + (hw + xv - u) * coef;
        us[(size_t)t * H_]  = u;
        spk[(size_t)t * H_] = s;
    }
}

// ----------------------------------------------------------------------------
// Tail: hys/hzs for t in [256,512) are the final (hy, hz), copied from t=255
// ----------------------------------------------------------------------------
__global__ void __launch_bounds__(256)
tail_kernel(float* __restrict__ out) {
    const int b  = blockIdx.x;
    const int tc = blockIdx.y;        // 8 chunks of 32 timesteps
    const int h4 = threadIdx.x;       // float4 index 0..255

    const float4 hyv = ((const float4*)(out + ((size_t)b * T_ + 255) * H_))[h4];
    const float4 hzv = ((const float4*)(out + OFF_HZS + ((size_t)b * T_ + 255) * H_))[h4];

    const int t0 = 256 + tc * 32;
    for (int tt = 0; tt < 32; ++tt) {
        size_t off = ((size_t)b * T_ + t0 + tt) * H_;
        ((float4*)(out + off))[h4]           = hyv;
        ((float4*)(out + OFF_HZS + off))[h4] = hzv;
    }
}

// ----------------------------------------------------------------------------
// Launch
// ----------------------------------------------------------------------------
extern "C" void kernel_launch(void* const* d_in, const int* in_sizes, int n_in,
                              void* d_out, int out_size) {
    (void)in_sizes; (void)n_in; (void)out_size;
    const float* x    = (const float*)d_in[0];
    const float* x2h  = (const float*)d_in[1];
    const float* h2h  = (const float*)d_in[2];
    const float* bias = (const float*)d_in[3];
    const float* gam  = (const float*)d_in[4];
    const float* eps  = (const float*)d_in[5];
    float* out = (float*)d_out;

    cudaFuncSetAttribute(harm_kernel<0>, cudaFuncAttributeMaxDynamicSharedMemorySize, SMEM_HARM);
    cudaFuncSetAttribute(harm_kernel<1>, cudaFuncAttributeMaxDynamicSharedMemorySize, SMEM_HARM);

    zero_kernel<<<128, 256>>>();
    xw_kernel<<<dim3(8, 512), 256>>>(x, x2h);

    for (int t = 0; t < TH_; ++t)
        harm_kernel<0><<<128, 256, SMEM_HARM>>>(t, t & 1, h2h, bias, gam, eps, out);

    // after 256 steps the final state sits in buffer 0
    harm_kernel<1><<<128, 256, SMEM_HARM>>>(0, 0, h2h, bias, gam, eps, out);

    spike_kernel<<<256, 256>>>(out);
    tail_kernel<<<dim3(64, 8), 256>>>(out);
}

// round 10
// speedup vs baseline: 1.0064x; 1.0033x over previous
#include <cuda_runtime.h>
#include <math.h>
#include <stdint.h>

// ----------------------------------------------------------------------------
// Problem constants
// ----------------------------------------------------------------------------
#define B_    64
#define T_    512
#define NI_   64
#define H_    1024
#define TH_   256          // T_HARM == T_SPIKE == 256
#define DTs   0.042f

static const size_t OFF_HZS = (size_t)B_ * T_ * H_;            // 33,554,432
static const size_t OFF_US  = 2ull * (size_t)B_ * T_ * H_;     // 67,108,864
static const size_t OFF_SPK = OFF_US + (size_t)B_ * TH_ * H_;  // 83,886,080

// ----------------------------------------------------------------------------
// Device scratch (static __device__ globals: allocation-free rule)
// ----------------------------------------------------------------------------
__device__ float  g_xw[(size_t)TH_ * B_ * H_];   // [t][b][h], 64 MB
__device__ float2 g_hy2[2][32 * H_];             // ping-pong hy, pair-packed [p][h]
__device__ float2 g_hz2[2][32 * H_];             // ping-pong hz
__device__ float  g_hyWf[B_ * H_];               // hy_final @ h2h, plain [b][h]

// ----------------------------------------------------------------------------
// Helpers
// ----------------------------------------------------------------------------
__device__ __forceinline__ float2 ffma2(float2 a, float2 b, float2 c) {
    float2 d;
    asm("fma.rn.f32x2 %0, %1, %2, %3;"
        : "=l"(*reinterpret_cast<unsigned long long*>(&d))
        : "l"(*reinterpret_cast<unsigned long long*>(&a)),
          "l"(*reinterpret_cast<unsigned long long*>(&b)),
          "l"(*reinterpret_cast<unsigned long long*>(&c)));
    return d;
}

// accurate tanh, safe under fast-math (no MUFU.TANH, no overflow)
__device__ __forceinline__ float tanh_acc(float x) {
    float a = 2.0f * fabsf(x);
    float e = expf(-a);                 // in (0,1]
    float t = (1.0f - e) / (1.0f + e);
    return copysignf(t, x);
}

__device__ __forceinline__ void cp_async16(void* smem, const void* gmem) {
    unsigned s = (unsigned)__cvta_generic_to_shared(smem);
    asm volatile("cp.async.cg.shared.global [%0], [%1], 16;" :: "r"(s), "l"(gmem) : "memory");
}
#define CP_COMMIT() asm volatile("cp.async.commit_group;" ::: "memory")
#define CP_WAIT0()  asm volatile("cp.async.wait_group 0;"  ::: "memory")

// ----------------------------------------------------------------------------
// Zero the initial state buffers (must run every launch: deterministic replay)
// ----------------------------------------------------------------------------
__global__ void zero_kernel() {
    int i = blockIdx.x * 256 + threadIdx.x;
    if (i < 32 * H_) {
        g_hy2[0][i] = make_float2(0.f, 0.f);
        g_hz2[0][i] = make_float2(0.f, 0.f);
    }
}

// ----------------------------------------------------------------------------
// xw[t][b][:] = x[b][t][:] @ x2h   for t < 256  (no bias)
// grid (8 col-tiles of 128, 512 row-tiles of 32), 256 threads
// rows r = t*64 + b  (b fastest)
// ----------------------------------------------------------------------------
__global__ void __launch_bounds__(256)
xw_kernel(const float* __restrict__ x, const float* __restrict__ x2h) {
    __shared__ float xs[32][68];     // [row][k], padded
    __shared__ float ws[64][128];    // [k][col]

    const int tid = threadIdx.x;
    const int j0  = blockIdx.x * 128;
    const int r0g = blockIdx.y * 32;

    // load x tile: 512 float4, 2 per thread
    #pragma unroll
    for (int u = 0; u < 2; ++u) {
        int n = u * 256 + tid;
        int r = n >> 4, k4 = n & 15;
        int rg = r0g + r;
        int b = rg & 63, tt = rg >> 6;
        float4 v = *(const float4*)(x + ((size_t)b * T_ + tt) * NI_ + k4 * 4);
        *(float4*)&xs[r][k4 * 4] = v;
    }
    // load w tile: 2048 float4, 8 per thread
    #pragma unroll
    for (int u = 0; u < 8; ++u) {
        int n = u * 256 + tid;
        int k = n >> 5, jg = n & 31;
        float4 v = *(const float4*)(x2h + (size_t)k * H_ + j0 + jg * 4);
        *(float4*)&ws[k][jg * 4] = v;
    }
    __syncthreads();

    const int jj0 = (tid & 31) * 4;
    const int r0  = (tid >> 5) * 4;
    float acc[4][4] = {};
    #pragma unroll 8
    for (int k = 0; k < 64; ++k) {
        float4 wv = *(const float4*)&ws[k][jj0];
        #pragma unroll
        for (int r = 0; r < 4; ++r) {
            float xv = xs[r0 + r][k];
            acc[r][0] = fmaf(xv, wv.x, acc[r][0]);
            acc[r][1] = fmaf(xv, wv.y, acc[r][1]);
            acc[r][2] = fmaf(xv, wv.z, acc[r][2]);
            acc[r][3] = fmaf(xv, wv.w, acc[r][3]);
        }
    }
    #pragma unroll
    for (int r = 0; r < 4; ++r) {
        int rg = r0g + r0 + r;
        float4 v = make_float4(acc[r][0], acc[r][1], acc[r][2], acc[r][3]);
        *(float4*)&g_xw[(size_t)rg * H_ + j0 + jj0] = v;
    }
}

// ----------------------------------------------------------------------------
// Harmonic step (MODE 0) / hyW GEMM (MODE 1)
//
// grid 128 blocks x 8 output columns, 256 threads (8 warps).
// GEMM: warp w covers K-slice (128 k's, spread as 32 per 256-k tile);
//       lane = batch pair p; each thread accumulates all 8 columns
//       as 4 column-pair float2 accs per batch (FFMA2).
// hy tiles (32 pairs x 256 k, float2) double-buffered via cp.async.
// ----------------------------------------------------------------------------
#define HY_ROW   516                          // 512 + 4 pad floats
#define HY_FLOATS (2 * 32 * HY_ROW)           // 33024
#define SMEM_HARM (HY_FLOATS * 4 + 1024 * 8 * 4 + 8 * 32 * 8 * 8)  // 181,248 B

__device__ __forceinline__ void load_hy_tile(const float* __restrict__ src,
                                             float* __restrict__ hyS,
                                             int kt, int bb, int tid) {
    // 4096 float4 per tile (32 rows x 128), 16 per thread
    #pragma unroll
    for (int u = 0; u < 16; ++u) {
        int n = u * 256 + tid;
        int p = n >> 7, q = n & 127;
        cp_async16(hyS + (size_t)(bb * 32 + p) * HY_ROW + 4 * q,
                   src + ((size_t)p * H_ + (size_t)kt * 256) * 2 + 4 * q);
    }
}

template<int MODE>
__global__ void __launch_bounds__(256, 1)
harm_kernel(int t, int par,
            const float* __restrict__ h2h,
            const float* __restrict__ bias,
            const float* __restrict__ gam,
            const float* __restrict__ eps,
            float* __restrict__ out) {
    extern __shared__ float sm[];
    float*  hyS = sm;                              // [2][32][HY_ROW]
    float*  w4  = sm + HY_FLOATS;                  // [1024][8]
    float2* red = (float2*)(w4 + 1024 * 8);        // [8][32][8]

    const int tid  = threadIdx.x;
    const int lane = tid & 31;
    const int w    = tid >> 5;
    const int j0   = blockIdx.x * 8;

    const float* hyIn = (const float*)g_hy2[par];

    // weights: w4[k][c] = h2h[k][j0+c]; 8 cp.async per thread
    #pragma unroll
    for (int u = 0; u < 8; ++u) {
        int n = u * 256 + tid;
        int k = n >> 1, half = (n & 1) * 4;
        cp_async16(w4 + (size_t)k * 8 + half, h2h + (size_t)k * H_ + j0 + half);
    }
    load_hy_tile(hyIn, hyS, 0, 0, tid);
    CP_COMMIT();
    CP_WAIT0();
    __syncthreads();

    // acc[0..3] = batch 2p, col-pairs (j0+2cp, j0+2cp+1); acc[4..7] = batch 2p+1
    float2 acc[8];
    #pragma unroll
    for (int c = 0; c < 8; ++c) acc[c] = make_float2(0.f, 0.f);

    for (int kt = 0; kt < 4; ++kt) {
        if (kt < 3) { load_hy_tile(hyIn, hyS, kt + 1, (kt + 1) & 1, tid); CP_COMMIT(); }

        const float* hrow = hyS + (size_t)((kt & 1) * 32 + lane) * HY_ROW;
        const int kb  = kt * 256;
        const int kk0 = w * 32;
        #pragma unroll
        for (int kk = kk0; kk < kk0 + 32; kk += 2) {
            float4 hv = *(const float4*)(hrow + 2 * kk);
            const float* wp = w4 + (size_t)(kb + kk) * 8;
            float4 wA = *(const float4*)(wp);        // cols 0-3 @ k
            float4 wB = *(const float4*)(wp + 4);    // cols 4-7 @ k
            float4 wC = *(const float4*)(wp + 8);    // cols 0-3 @ k+1
            float4 wD = *(const float4*)(wp + 12);   // cols 4-7 @ k+1

            float2 b0k0 = make_float2(hv.x, hv.x);
            float2 b1k0 = make_float2(hv.y, hv.y);
            float2 b0k1 = make_float2(hv.z, hv.z);
            float2 b1k1 = make_float2(hv.w, hv.w);

            acc[0] = ffma2(b0k0, make_float2(wA.x, wA.y), acc[0]);
            acc[1] = ffma2(b0k0, make_float2(wA.z, wA.w), acc[1]);
            acc[2] = ffma2(b0k0, make_float2(wB.x, wB.y), acc[2]);
            acc[3] = ffma2(b0k0, make_float2(wB.z, wB.w), acc[3]);
            acc[4] = ffma2(b1k0, make_float2(wA.x, wA.y), acc[4]);
            acc[5] = ffma2(b1k0, make_float2(wA.z, wA.w), acc[5]);
            acc[6] = ffma2(b1k0, make_float2(wB.x, wB.y), acc[6]);
            acc[7] = ffma2(b1k0, make_float2(wB.z, wB.w), acc[7]);

            acc[0] = ffma2(b0k1, make_float2(wC.x, wC.y), acc[0]);
            acc[1] = ffma2(b0k1, make_float2(wC.z, wC.w), acc[1]);
            acc[2] = ffma2(b0k1, make_float2(wD.x, wD.y), acc[2]);
            acc[3] = ffma2(b0k1, make_float2(wD.z, wD.w), acc[3]);
            acc[4] = ffma2(b1k1, make_float2(wC.x, wC.y), acc[4]);
            acc[5] = ffma2(b1k1, make_float2(wC.z, wC.w), acc[5]);
            acc[6] = ffma2(b1k1, make_float2(wD.x, wD.y), acc[6]);
            acc[7] = ffma2(b1k1, make_float2(wD.z, wD.w), acc[7]);
        }
        if (kt < 3) CP_WAIT0();
        __syncthreads();
    }

    // cross-warp (K-split) reduction via smem
    #pragma unroll
    for (int c = 0; c < 8; ++c) red[(size_t)(w * 32 + lane) * 8 + c] = acc[c];
    __syncthreads();

    // finish: thread (p, c) handles batches (2p, 2p+1) at column j0+c
    const int p    = tid >> 3;
    const int c    = tid & 7;
    const int cp   = c >> 1;
    const int comp = c & 1;

    float s0 = 0.f, s1 = 0.f;
    #pragma unroll
    for (int kh = 0; kh < 8; ++kh) {
        float2 e0 = red[(size_t)(kh * 32 + p) * 8 + cp];      // batch 2p
        float2 e1 = red[(size_t)(kh * 32 + p) * 8 + 4 + cp];  // batch 2p+1
        s0 += comp ? e0.y : e0.x;
        s1 += comp ? e1.y : e1.x;
    }

    const int j  = j0 + c;
    const int b0 = 2 * p;

    if (MODE == 1) {
        g_hyWf[(size_t)b0 * H_ + j]       = s0;
        g_hyWf[(size_t)(b0 + 1) * H_ + j] = s1;
        return;
    }

    const float bj = bias[j], gj = gam[j], ej = eps[j];
    const float* xwrow = g_xw + ((size_t)t * B_ + b0) * H_ + j;
    const float x0 = xwrow[0];
    const float x1 = xwrow[H_];

    float2 hyo = g_hy2[par][(size_t)p * H_ + j];
    float2 hzo = g_hz2[par][(size_t)p * H_ + j];

    float th0 = tanh_acc(s0 + x0 + bj);
    float th1 = tanh_acc(s1 + x1 + bj);

    float hz0 = hzo.x + DTs * (th0 - gj * hyo.x - ej * hzo.x);
    float hz1 = hzo.y + DTs * (th1 - gj * hyo.y - ej * hzo.y);
    float hy0 = hyo.x + DTs * hz0;
    float hy1 = hyo.y + DTs * hz1;

    const int np = par ^ 1;
    g_hy2[np][(size_t)p * H_ + j] = make_float2(hy0, hy1);
    g_hz2[np][(size_t)p * H_ + j] = make_float2(hz0, hz1);

    out[((size_t)b0 * T_ + t) * H_ + j]                 = hy0;
    out[((size_t)(b0 + 1) * T_ + t) * H_ + j]           = hy1;
    out[OFF_HZS + ((size_t)b0 * T_ + t) * H_ + j]       = hz0;
    out[OFF_HZS + ((size_t)(b0 + 1) * T_ + t) * H_ + j] = hz1;
}

// ----------------------------------------------------------------------------
// Spiking phase: fully parallel over (b, h); 256 sequential steps per thread
// ----------------------------------------------------------------------------
__global__ void __launch_bounds__(256)
spike_kernel(float* __restrict__ out) {
    const int idx = blockIdx.x * 256 + threadIdx.x;   // 0..65535 = b*1024 + h
    const int b = idx >> 10, h = idx & 1023;

    const float hw = g_hyWf[idx];
    const float coef = (5.0f * 0.005f) * 0.042f;      // R*C*DT

    const float* xw  = g_xw + (size_t)b * H_ + h;     // + t*B_*H_
    float* us  = out + OFF_US  + (size_t)b * TH_ * H_ + h;
    float* spk = out + OFF_SPK + (size_t)b * TH_ * H_ + h;

    float u = 0.f;
    for (int t = 0; t < TH_; ++t) {
        float xv = xw[(size_t)t * (B_ * H_)];
        float s  = (u > 0.008f) ? 1.0f : 0.0f;
        if (u > 0.008f) u = 0.001f;
        u = u + (hw + xv - u) * coef;
        us[(size_t)t * H_]  = u;
        spk[(size_t)t * H_] = s;
    }
}

// ----------------------------------------------------------------------------
// Tail: hys/hzs for t in [256,512) are the final (hy, hz), copied from t=255
// ----------------------------------------------------------------------------
__global__ void __launch_bounds__(256)
tail_kernel(float* __restrict__ out) {
    const int b  = blockIdx.x;
    const int tc = blockIdx.y;        // 8 chunks of 32 timesteps
    const int h4 = threadIdx.x;       // float4 index 0..255

    const float4 hyv = ((const float4*)(out + ((size_t)b * T_ + 255) * H_))[h4];
    const float4 hzv = ((const float4*)(out + OFF_HZS + ((size_t)b * T_ + 255) * H_))[h4];

    const int t0 = 256 + tc * 32;
    for (int tt = 0; tt < 32; ++tt) {
        size_t off = ((size_t)b * T_ + t0 + tt) * H_;
        ((float4*)(out + off))[h4]           = hyv;
        ((float4*)(out + OFF_HZS + off))[h4] = hzv;
    }
}

// ----------------------------------------------------------------------------
// Launch
// ----------------------------------------------------------------------------
extern "C" void kernel_launch(void* const* d_in, const int* in_sizes, int n_in,
                              void* d_out, int out_size) {
    (void)in_sizes; (void)n_in; (void)out_size;
    const float* x    = (const float*)d_in[0];
    const float* x2h  = (const float*)d_in[1];
    const float* h2h  = (const float*)d_in[2];
    const float* bias = (const float*)d_in[3];
    const float* gam  = (const float*)d_in[4];
    const float* eps  = (const float*)d_in[5];
    float* out = (float*)d_out;

    cudaFuncSetAttribute(harm_kernel<0>, cudaFuncAttributeMaxDynamicSharedMemorySize, SMEM_HARM);
    cudaFuncSetAttribute(harm_kernel<1>, cudaFuncAttributeMaxDynamicSharedMemorySize, SMEM_HARM);

    zero_kernel<<<128, 256>>>();
    xw_kernel<<<dim3(8, 512), 256>>>(x, x2h);

    for (int t = 0; t < TH_; ++t)
        harm_kernel<0><<<128, 256, SMEM_HARM>>>(t, t & 1, h2h, bias, gam, eps, out);

    // after 256 steps the final state sits in buffer 0
    harm_kernel<1><<<128, 256, SMEM_HARM>>>(0, 0, h2h, bias, gam, eps, out);

    spike_kernel<<<256, 256>>>(out);
    tail_kernel<<<dim3(64, 8), 256>>>(out);
}